// round 1
// baseline (speedup 1.0000x reference)
#include <cuda_runtime.h>
#include <math.h>

#define NN 50000
#define EE 400000
#define DD 64
#define HH 4
#define CC 64
#define HC 256
#define EDD 16

typedef unsigned long long ull;

// ---------------- static scratch (no allocations allowed) ----------------
__device__ __align__(16) float g_xl[(size_t)NN * HC];   // 51.2 MB
__device__ __align__(16) float g_xr[(size_t)NN * HC];   // 51.2 MB
__device__ __align__(16) float g_mid[(size_t)NN * DD];  // 12.8 MB
__device__ int g_cnt[NN];
__device__ int g_cursor[NN];
__device__ int g_rowptr[NN + 1];
__device__ int g_esrc[EE];
__device__ int g_eord[EE];

// ---------------- packed f32x2 helpers (sm_103a) ----------------
__device__ __forceinline__ ull pk2(float a, float b) {
    ull r; asm("mov.b64 %0, {%1, %2};" : "=l"(r) : "f"(a), "f"(b)); return r;
}
__device__ __forceinline__ float2 up2(ull v) {
    float2 r; asm("mov.b64 {%0, %1}, %2;" : "=f"(r.x), "=f"(r.y) : "l"(v)); return r;
}
__device__ __forceinline__ ull fma2(ull a, ull b, ull c) {
    ull d; asm("fma.rn.f32x2 %0, %1, %2, %3;" : "=l"(d) : "l"(a), "l"(b), "l"(c)); return d;
}

// ---------------- CSR build ----------------
__global__ void zero_cnt_kernel() {
    int i = blockIdx.x * blockDim.x + threadIdx.x;
    if (i < NN) g_cnt[i] = 0;
}

__global__ void hist_kernel(const int* __restrict__ dst) {
    int e = blockIdx.x * blockDim.x + threadIdx.x;
    if (e < EE) atomicAdd(&g_cnt[dst[e]], 1);
}

__global__ void scan_kernel() {
    __shared__ int sh[1024];
    int tid = threadIdx.x;
    int carry = 0;
    for (int base = 0; base < NN; base += 1024) {
        int v = (base + tid < NN) ? g_cnt[base + tid] : 0;
        sh[tid] = v;
        __syncthreads();
        for (int off = 1; off < 1024; off <<= 1) {
            int t = (tid >= off) ? sh[tid - off] : 0;
            __syncthreads();
            sh[tid] += t;
            __syncthreads();
        }
        if (base + tid < NN) {
            int excl = carry + sh[tid] - v;
            g_rowptr[base + tid] = excl;
            g_cursor[base + tid] = excl;
        }
        carry += sh[1023];
        __syncthreads();
    }
    if (tid == 0) g_rowptr[NN] = carry;
}

__global__ void scatter_kernel(const int* __restrict__ src, const int* __restrict__ dst) {
    int e = blockIdx.x * blockDim.x + threadIdx.x;
    if (e < EE) {
        int d = dst[e];
        int pos = atomicAdd(&g_cursor[d], 1);
        g_esrc[pos] = src[e];
        g_eord[pos] = e;
    }
}

// ---------------- node transform: xl = x@Wl + bl, xr = x@Wr + br ----------------
// block = 256 threads (one per output column j), processes 64 nodes.
__global__ __launch_bounds__(256) void transform_kernel(
    const float* __restrict__ x,  // [N,64] or nullptr -> g_mid
    const float* __restrict__ Wl, const float* __restrict__ bl,
    const float* __restrict__ Wr, const float* __restrict__ br)
{
    __shared__ __align__(16) float hs[64][64];
    const float* xp = x ? x : g_mid;
    int j = threadIdx.x;
    int n0 = blockIdx.x * 64;

    // register-cache W columns, packed along k
    ull wl2[32], wr2[32];
#pragma unroll
    for (int q = 0; q < 32; q++) {
        wl2[q] = pk2(Wl[(2 * q) * HC + j], Wl[(2 * q + 1) * HC + j]);
        wr2[q] = pk2(Wr[(2 * q) * HC + j], Wr[(2 * q + 1) * HC + j]);
    }
    float blj = bl[j], brj = br[j];

    for (int t = j; t < 64 * 64; t += 256) {
        int n = t >> 6, k = t & 63;
        hs[n][k] = (n0 + n < NN) ? xp[(size_t)(n0 + n) * DD + k] : 0.f;
    }
    __syncthreads();

    int nmax = NN - n0; if (nmax > 64) nmax = 64;
    for (int n = 0; n < nmax; n++) {
        const float2* hrow = (const float2*)hs[n];
        ull aL0 = 0, aL1 = 0, aR0 = 0, aR1 = 0;
#pragma unroll
        for (int q = 0; q < 32; q += 2) {
            float2 h0f = hrow[q], h1f = hrow[q + 1];
            ull h0 = pk2(h0f.x, h0f.y), h1 = pk2(h1f.x, h1f.y);
            aL0 = fma2(h0, wl2[q], aL0);
            aL1 = fma2(h1, wl2[q + 1], aL1);
            aR0 = fma2(h0, wr2[q], aR0);
            aR1 = fma2(h1, wr2[q + 1], aR1);
        }
        float2 l0 = up2(aL0), l1 = up2(aL1), r0 = up2(aR0), r1 = up2(aR1);
        size_t idx = (size_t)(n0 + n) * HC + j;
        g_xl[idx] = blj + (l0.x + l0.y) + (l1.x + l1.y);
        g_xr[idx] = brj + (r0.x + r0.y) + (r1.x + r1.y);
    }
}

// ---------------- fused GATv2 aggregate + head-mean + bias + LN + (residual) + GELU ----
// one warp per destination node; lane owns 8 contiguous channels (cc = lane*8 + i)
// head = lane/8 (8 lanes per head, 64 channels per head)
__global__ __launch_bounds__(128) void gat_kernel(
    const float* __restrict__ edge_attr,  // [E,16]
    const float* __restrict__ We,         // [16,256]
    const float* __restrict__ att,        // [4,64]
    const float* __restrict__ bias,       // [64]
    const float* __restrict__ lng, const float* __restrict__ lnb,
    const float* __restrict__ residual,   // null for layer 1
    float* __restrict__ out_ext, int use_ext)
{
    int gw = (blockIdx.x * blockDim.x + threadIdx.x) >> 5;
    int lane = threadIdx.x & 31;
    if (gw >= NN) return;
    int n = gw;
    float* out = use_ext ? out_ext : g_mid;

    int cb = lane * 8;              // global channel base for this lane
    int hd = lane >> 3;             // head index
    int hcb = (lane & 7) * 8;       // within-head channel base

    // register-cache We slice: [16][8ch] as packed pairs
    ull wep[16][4];
#pragma unroll
    for (int k = 0; k < EDD; k++) {
        const float2* wr = (const float2*)(We + k * HC + cb);
#pragma unroll
        for (int j = 0; j < 4; j++) { float2 w = wr[j]; wep[k][j] = pk2(w.x, w.y); }
    }
    float attv[8];
#pragma unroll
    for (int i = 0; i < 8; i++) attv[i] = att[hd * CC + hcb + i];

    float xr[8];
    {
        const float4* p = (const float4*)(g_xr + (size_t)n * HC + cb);
        float4 a = p[0], b = p[1];
        xr[0] = a.x; xr[1] = a.y; xr[2] = a.z; xr[3] = a.w;
        xr[4] = b.x; xr[5] = b.y; xr[6] = b.z; xr[7] = b.w;
    }

    ull acc[4] = {0, 0, 0, 0};
    float den = 0.f;
    int e0 = g_rowptr[n], e1 = g_rowptr[n + 1];

    for (int e = e0; e < e1; e++) {
        int s = g_esrc[e];
        int eid = g_eord[e];
        float eav = (lane < EDD) ? __ldg(edge_attr + (size_t)eid * EDD + lane) : 0.f;

        float xl[8];
        {
            const float4* p = (const float4*)(g_xl + (size_t)s * HC + cb);
            float4 a = p[0], b = p[1];
            xl[0] = a.x; xl[1] = a.y; xl[2] = a.z; xl[3] = a.w;
            xl[4] = b.x; xl[5] = b.y; xl[6] = b.z; xl[7] = b.w;
        }

        // ez = edge_attr @ We (on the fly, packed)
        ull ez[4] = {0, 0, 0, 0};
#pragma unroll
        for (int k = 0; k < EDD; k++) {
            float eak = __shfl_sync(0xffffffffu, eav, k);
            ull e2 = pk2(eak, eak);
#pragma unroll
            for (int j = 0; j < 4; j++) ez[j] = fma2(wep[k][j], e2, ez[j]);
        }

        // s = leaky_relu(xl + xr + ez); alpha partial = dot(s, att)
        float ap = 0.f;
#pragma unroll
        for (int j = 0; j < 4; j++) {
            float2 ef = up2(ez[j]);
            float s0 = xl[2 * j] + xr[2 * j] + ef.x;
            float s1 = xl[2 * j + 1] + xr[2 * j + 1] + ef.y;
            s0 = s0 > 0.f ? s0 : 0.2f * s0;
            s1 = s1 > 0.f ? s1 : 0.2f * s1;
            ap = fmaf(s0, attv[2 * j], ap);
            ap = fmaf(s1, attv[2 * j + 1], ap);
        }
        // per-head reduce (8 lanes/head)
        ap += __shfl_xor_sync(0xffffffffu, ap, 1);
        ap += __shfl_xor_sync(0xffffffffu, ap, 2);
        ap += __shfl_xor_sync(0xffffffffu, ap, 4);

        // softmax without max-subtraction: scale-invariant, logits are O(+-8)
        float ex = __expf(ap);
        den += ex;
        ull ex2 = pk2(ex, ex);
#pragma unroll
        for (int j = 0; j < 4; j++) {
            ull xl2 = pk2(xl[2 * j], xl[2 * j + 1]);
            acc[j] = fma2(xl2, ex2, acc[j]);
        }
    }

    // normalize (per head), head-mean, bias
    float inv = 1.f / (den + 1e-16f);
    float r[8];
#pragma unroll
    for (int j = 0; j < 4; j++) {
        float2 af = up2(acc[j]);
        r[2 * j] = af.x * inv;
        r[2 * j + 1] = af.y * inv;
    }
#pragma unroll
    for (int i = 0; i < 8; i++) {
        r[i] += __shfl_xor_sync(0xffffffffu, r[i], 8);
        r[i] += __shfl_xor_sync(0xffffffffu, r[i], 16);
        r[i] = 0.25f * r[i] + bias[hcb + i];
    }

    // LayerNorm over 64 channels (all 4 lane-groups hold identical copies)
    float m = 0.f;
#pragma unroll
    for (int i = 0; i < 8; i++) m += r[i];
    m += __shfl_xor_sync(0xffffffffu, m, 1);
    m += __shfl_xor_sync(0xffffffffu, m, 2);
    m += __shfl_xor_sync(0xffffffffu, m, 4);
    m *= (1.f / 64.f);
    float v = 0.f;
#pragma unroll
    for (int i = 0; i < 8; i++) { float d = r[i] - m; v = fmaf(d, d, v); }
    v += __shfl_xor_sync(0xffffffffu, v, 1);
    v += __shfl_xor_sync(0xffffffffu, v, 2);
    v += __shfl_xor_sync(0xffffffffu, v, 4);
    v *= (1.f / 64.f);
    float rstd = rsqrtf(v + 1e-5f);

    if (lane < 8) {
        float o[8];
#pragma unroll
        for (int i = 0; i < 8; i++) {
            int c = hcb + i;  // lane<8 -> hcb == lane*8, covers channels 0..63
            float y = (r[i] - m) * rstd * lng[c] + lnb[c];
            if (residual) y += residual[(size_t)n * DD + c];
            o[i] = 0.5f * y * (1.f + erff(y * 0.70710678118654752f));  // exact GELU
        }
        float4* op = (float4*)(out + (size_t)n * DD + hcb);
        op[0] = make_float4(o[0], o[1], o[2], o[3]);
        op[1] = make_float4(o[4], o[5], o[6], o[7]);
    }
}

// ---------------- launch ----------------
extern "C" void kernel_launch(void* const* d_in, const int* in_sizes, int n_in,
                              void* d_out, int out_size) {
    const float* h      = (const float*)d_in[0];
    const int*   ei     = (const int*)d_in[1];
    const float* ea     = (const float*)d_in[2];
    const float* g1_Wl  = (const float*)d_in[3];
    const float* g1_bl  = (const float*)d_in[4];
    const float* g1_Wr  = (const float*)d_in[5];
    const float* g1_br  = (const float*)d_in[6];
    const float* g1_We  = (const float*)d_in[7];
    const float* g1_att = (const float*)d_in[8];
    const float* g1_bias= (const float*)d_in[9];
    const float* ln1_g  = (const float*)d_in[10];
    const float* ln1_b  = (const float*)d_in[11];
    const float* g2_Wl  = (const float*)d_in[12];
    const float* g2_bl  = (const float*)d_in[13];
    const float* g2_Wr  = (const float*)d_in[14];
    const float* g2_br  = (const float*)d_in[15];
    const float* g2_We  = (const float*)d_in[16];
    const float* g2_att = (const float*)d_in[17];
    const float* g2_bias= (const float*)d_in[18];
    const float* ln2_g  = (const float*)d_in[19];
    const float* ln2_b  = (const float*)d_in[20];
    float* out = (float*)d_out;

    const int* src = ei;        // edge_index[0]
    const int* dst = ei + EE;   // edge_index[1]

    // CSR build (deterministic work; segment sums are order-robust at 1e-3 tol)
    zero_cnt_kernel<<<(NN + 255) / 256, 256>>>();
    hist_kernel<<<(EE + 255) / 256, 256>>>(dst);
    scan_kernel<<<1, 1024>>>();
    scatter_kernel<<<(EE + 255) / 256, 256>>>(src, dst);

    // layer 1
    transform_kernel<<<(NN + 63) / 64, 256>>>(h, g1_Wl, g1_bl, g1_Wr, g1_br);
    gat_kernel<<<(NN + 3) / 4, 128>>>(ea, g1_We, g1_att, g1_bias, ln1_g, ln1_b,
                                      nullptr, nullptr, 0);
    // layer 2
    transform_kernel<<<(NN + 63) / 64, 256>>>(nullptr, g2_Wl, g2_bl, g2_Wr, g2_br);
    gat_kernel<<<(NN + 3) / 4, 128>>>(ea, g2_We, g2_att, g2_bias, ln2_g, ln2_b,
                                      h, out, 1);
}

// round 3
// speedup vs baseline: 1.4750x; 1.4750x over previous
#include <cuda_runtime.h>
#include <math.h>

#define NN 50000
#define EE 400000
#define DD 64
#define HH 4
#define CC 64
#define HC 256
#define EDD 16

typedef unsigned long long ull;

// ---------------- static scratch ----------------
__device__ __align__(16) float g_xl[(size_t)NN * HC];
__device__ __align__(16) float g_xr[(size_t)NN * HC];
__device__ __align__(16) float g_mid[(size_t)NN * DD];
__device__ int g_cnt[NN];
__device__ int g_cursor[NN];
__device__ int g_rowptr[NN + 1];
__device__ int g_esrc[EE];
__device__ int g_eord[EE];

// ---------------- packed f32x2 helpers ----------------
__device__ __forceinline__ ull pk2(float a, float b) {
    ull r; asm("mov.b64 %0, {%1, %2};" : "=l"(r) : "f"(a), "f"(b)); return r;
}
__device__ __forceinline__ ull dup2(float a) {
    ull r; asm("mov.b64 %0, {%1, %1};" : "=l"(r) : "f"(a)); return r;
}
__device__ __forceinline__ float2 up2(ull v) {
    float2 r; asm("mov.b64 {%0, %1}, %2;" : "=f"(r.x), "=f"(r.y) : "l"(v)); return r;
}
__device__ __forceinline__ ull fma2(ull a, ull b, ull c) {
    ull d; asm("fma.rn.f32x2 %0, %1, %2, %3;" : "=l"(d) : "l"(a), "l"(b), "l"(c)); return d;
}
__device__ __forceinline__ ull add2(ull a, ull b) {
    ull d; asm("add.rn.f32x2 %0, %1, %2;" : "=l"(d) : "l"(a), "l"(b)); return d;
}

// ---------------- CSR build ----------------
__global__ void zero_cnt_kernel() {
    int i = blockIdx.x * blockDim.x + threadIdx.x;
    if (i < NN) g_cnt[i] = 0;
}

__global__ void hist_kernel(const int* __restrict__ dst) {
    int e = blockIdx.x * blockDim.x + threadIdx.x;
    if (e < EE) atomicAdd(&g_cnt[dst[e]], 1);
}

// single-block scan: 1024 threads, 49 elements each (49*1024 >= NN)
__global__ __launch_bounds__(1024) void scan_kernel() {
    __shared__ int wsum[32];
    int t = threadIdx.x;
    int lane = t & 31, wid = t >> 5;
    const int PER = 49;
    int base = t * PER;

    int s = 0;
#pragma unroll 7
    for (int i = 0; i < PER; i++) {
        int idx = base + i;
        if (idx < NN) s += g_cnt[idx];
    }
    int ws = s;
#pragma unroll
    for (int off = 1; off < 32; off <<= 1) {
        int v = __shfl_up_sync(0xffffffffu, ws, off);
        if (lane >= off) ws += v;
    }
    if (lane == 31) wsum[wid] = ws;
    __syncthreads();
    if (wid == 0) {
        int v = wsum[lane];
        int iv = v;
#pragma unroll
        for (int off = 1; off < 32; off <<= 1) {
            int u = __shfl_up_sync(0xffffffffu, iv, off);
            if (lane >= off) iv += u;
        }
        wsum[lane] = iv - v;  // exclusive
    }
    __syncthreads();
    int offset = wsum[wid] + (ws - s);

    int run = offset;
#pragma unroll 7
    for (int i = 0; i < PER; i++) {
        int idx = base + i;
        if (idx < NN) {
            int v = g_cnt[idx];
            g_rowptr[idx] = run;
            g_cursor[idx] = run;
            run += v;
        }
    }
    if (t == 1023) g_rowptr[NN] = run;
}

__global__ void scatter_kernel(const int* __restrict__ src, const int* __restrict__ dst) {
    int e = blockIdx.x * blockDim.x + threadIdx.x;
    if (e < EE) {
        int d = dst[e];
        int pos = atomicAdd(&g_cursor[d], 1);
        g_esrc[pos] = src[e];
        g_eord[pos] = e;
    }
}

// ---------------- node transform: xl = x@Wl+bl, xr = x@Wr+br ----------------
// 512 threads: tid 0-255 -> column j of Wl, tid 256-511 -> column j of Wr.
__global__ __launch_bounds__(512) void transform_kernel(
    const float* __restrict__ x,  // null -> g_mid
    const float* __restrict__ Wl, const float* __restrict__ bl,
    const float* __restrict__ Wr, const float* __restrict__ br)
{
    __shared__ __align__(16) float hs[64 * 64];
    const float* xp = x ? x : g_mid;
    int tid = threadIdx.x;
    int j = tid & 255;
    int isR = tid >> 8;
    const float* W = isR ? Wr : Wl;
    float bj = isR ? br[j] : bl[j];
    float* ob = isR ? g_xr : g_xl;
    int n0 = blockIdx.x * 64;

    ull w2[32];
#pragma unroll
    for (int q = 0; q < 32; q++)
        w2[q] = pk2(W[(2 * q) * HC + j], W[(2 * q + 1) * HC + j]);

    const float4* src4 = (const float4*)(xp + (size_t)n0 * DD);
    int limit4 = (NN - n0) * (DD / 4);
    for (int i = tid; i < 1024; i += 512) {
        float4 v = (i < limit4) ? src4[i] : make_float4(0.f, 0.f, 0.f, 0.f);
        ((float4*)hs)[i] = v;
    }
    __syncthreads();

    int nmax = NN - n0; if (nmax > 64) nmax = 64;
    for (int n = 0; n < nmax; n++) {
        const float4* hrow = (const float4*)(hs + n * 64);
        ull a0 = 0, a1 = 0, a2 = 0, a3 = 0;
#pragma unroll
        for (int q = 0; q < 16; q += 2) {
            float4 h0 = hrow[q], h1 = hrow[q + 1];
            a0 = fma2(pk2(h0.x, h0.y), w2[2 * q + 0], a0);
            a1 = fma2(pk2(h0.z, h0.w), w2[2 * q + 1], a1);
            a2 = fma2(pk2(h1.x, h1.y), w2[2 * q + 2], a2);
            a3 = fma2(pk2(h1.z, h1.w), w2[2 * q + 3], a3);
        }
        float2 f0 = up2(a0), f1 = up2(a1), f2 = up2(a2), f3 = up2(a3);
        ob[(size_t)(n0 + n) * HC + j] =
            bj + ((f0.x + f0.y) + (f1.x + f1.y)) + ((f2.x + f2.y) + (f3.x + f3.y));
    }
}

// ---------------- fused GATv2 aggregate + head-mean + bias + LN + res + GELU ----
// block = 64 threads = 2 warps per node (grid-stride over nodes).
// warp w handles heads {2w, 2w+1}: lanes 0-15 -> first head, 16-31 -> second.
// lane owns 4 channels within its head: hcb = (lane&15)*4.
__global__ __launch_bounds__(64) void gat_kernel(
    const float* __restrict__ edge_attr,  // [E,16]
    const float* __restrict__ We,         // [16,256]
    const float* __restrict__ att,        // [4,64]
    const float* __restrict__ bias,       // [64]
    const float* __restrict__ lng, const float* __restrict__ lnb,
    const float* __restrict__ residual,   // null for layer 1
    float* __restrict__ out_ext, int use_ext)
{
    __shared__ float sh[64];
    int warp = threadIdx.x >> 5;
    int lane = threadIdx.x & 31;
    int head = warp * 2 + (lane >> 4);
    int hcb = (lane & 15) * 4;
    int cb = head * CC + hcb;
    float* out = use_ext ? out_ext : g_mid;

    // We slice for my 4 channels: [16][2] packed pairs (64 regs)
    ull wep0[16], wep1[16];
#pragma unroll
    for (int k = 0; k < EDD; k++) {
        float4 w = *(const float4*)(We + k * HC + cb);
        wep0[k] = pk2(w.x, w.y);
        wep1[k] = pk2(w.z, w.w);
    }
    float4 attv = *(const float4*)(att + head * CC + hcb);
    float4 bi4 = *(const float4*)(bias + hcb);
    float4 lg4 = *(const float4*)(lng + hcb);
    float4 lb4 = *(const float4*)(lnb + hcb);

    for (int n = blockIdx.x; n < NN; n += gridDim.x) {
        int e0 = g_rowptr[n], e1 = g_rowptr[n + 1];

        float4 xr4 = *(const float4*)(g_xr + (size_t)n * HC + cb);
        ull xr2a = pk2(xr4.x, xr4.y), xr2b = pk2(xr4.z, xr4.w);

        ull acc0 = 0, acc1 = 0;
        float den = 0.f;

        int e = e0;
        float eav = 0.f;
        float4 xl4 = make_float4(0.f, 0.f, 0.f, 0.f);
        if (e < e1) {
            int s = g_esrc[e];
            int eid = g_eord[e];
            if (lane < EDD) eav = __ldg(edge_attr + (size_t)eid * EDD + lane);
            xl4 = *(const float4*)(g_xl + (size_t)s * HC + cb);
        }
        while (e < e1) {
            // prefetch next edge
            int en = e + 1;
            float eav2 = 0.f;
            float4 xl42 = make_float4(0.f, 0.f, 0.f, 0.f);
            if (en < e1) {
                int s2 = g_esrc[en];
                int eid2 = g_eord[en];
                if (lane < EDD) eav2 = __ldg(edge_attr + (size_t)eid2 * EDD + lane);
                xl42 = *(const float4*)(g_xl + (size_t)s2 * HC + cb);
            }

            ull xl2a = pk2(xl4.x, xl4.y), xl2b = pk2(xl4.z, xl4.w);

            // ez = ea @ We (my 4 channels)
            ull ez0 = 0, ez1 = 0;
#pragma unroll
            for (int k = 0; k < EDD; k++) {
                ull ek2 = dup2(__shfl_sync(0xffffffffu, eav, k));
                ez0 = fma2(wep0[k], ek2, ez0);
                ez1 = fma2(wep1[k], ek2, ez1);
            }
            // y = xl + xr + ez ; leaky ; dot with att
            float2 y0 = up2(add2(add2(xl2a, xr2a), ez0));
            float2 y1 = up2(add2(add2(xl2b, xr2b), ez1));
            float l0 = fmaxf(y0.x, 0.2f * y0.x);
            float l1 = fmaxf(y0.y, 0.2f * y0.y);
            float l2 = fmaxf(y1.x, 0.2f * y1.x);
            float l3 = fmaxf(y1.y, 0.2f * y1.y);
            float ap = l0 * attv.x;
            ap = fmaf(l1, attv.y, ap);
            ap = fmaf(l2, attv.z, ap);
            ap = fmaf(l3, attv.w, ap);
            // reduce over the 16 lanes of this head (all 32 lanes execute)
            ap += __shfl_xor_sync(0xffffffffu, ap, 1);
            ap += __shfl_xor_sync(0xffffffffu, ap, 2);
            ap += __shfl_xor_sync(0xffffffffu, ap, 4);
            ap += __shfl_xor_sync(0xffffffffu, ap, 8);

            float ex = __expf(ap);  // softmax w/o max-shift: scale-invariant, logits O(+-8)
            den += ex;
            ull ex2 = dup2(ex);
            acc0 = fma2(xl2a, ex2, acc0);
            acc1 = fma2(xl2b, ex2, acc1);

            eav = eav2; xl4 = xl42; e = en;
        }

        // normalize per head
        float inv = 1.f / (den + 1e-16f);
        float2 a0 = up2(acc0), a1 = up2(acc1);
        float r0 = a0.x * inv, r1 = a0.y * inv, r2 = a1.x * inv, r3 = a1.y * inv;

        // sum the two heads held by this warp (all 32 lanes execute)
        r0 += __shfl_xor_sync(0xffffffffu, r0, 16);
        r1 += __shfl_xor_sync(0xffffffffu, r1, 16);
        r2 += __shfl_xor_sync(0xffffffffu, r2, 16);
        r3 += __shfl_xor_sync(0xffffffffu, r3, 16);

        if (warp == 1 && lane < 16)
            *(float4*)(sh + hcb) = make_float4(r0, r1, r2, r3);
        __syncthreads();
        if (warp == 0 && lane < 16) {
            // NOTE: only lanes 0-15 execute from here on -> mask must be 0xffff
            const unsigned M16 = 0x0000ffffu;
            float4 o = *(const float4*)(sh + hcb);
            r0 = 0.25f * (r0 + o.x) + bi4.x;
            r1 = 0.25f * (r1 + o.y) + bi4.y;
            r2 = 0.25f * (r2 + o.z) + bi4.z;
            r3 = 0.25f * (r3 + o.w) + bi4.w;
            // LayerNorm over 64 channels spread across 16 lanes
            float m = r0 + r1 + r2 + r3;
            m += __shfl_xor_sync(M16, m, 1);
            m += __shfl_xor_sync(M16, m, 2);
            m += __shfl_xor_sync(M16, m, 4);
            m += __shfl_xor_sync(M16, m, 8);
            m *= (1.f / 64.f);
            float d0 = r0 - m, d1 = r1 - m, d2 = r2 - m, d3 = r3 - m;
            float v = d0 * d0;
            v = fmaf(d1, d1, v); v = fmaf(d2, d2, v); v = fmaf(d3, d3, v);
            v += __shfl_xor_sync(M16, v, 1);
            v += __shfl_xor_sync(M16, v, 2);
            v += __shfl_xor_sync(M16, v, 4);
            v += __shfl_xor_sync(M16, v, 8);
            v *= (1.f / 64.f);
            float rstd = rsqrtf(v + 1e-5f);

            float y0 = d0 * rstd * lg4.x + lb4.x;
            float y1 = d1 * rstd * lg4.y + lb4.y;
            float y2 = d2 * rstd * lg4.z + lb4.z;
            float y3 = d3 * rstd * lg4.w + lb4.w;
            if (residual) {
                float4 rs = *(const float4*)(residual + (size_t)n * DD + hcb);
                y0 += rs.x; y1 += rs.y; y2 += rs.z; y3 += rs.w;
            }
            const float ks = 0.70710678118654752f;
            float o0 = 0.5f * y0 * (1.f + erff(y0 * ks));
            float o1 = 0.5f * y1 * (1.f + erff(y1 * ks));
            float o2 = 0.5f * y2 * (1.f + erff(y2 * ks));
            float o3 = 0.5f * y3 * (1.f + erff(y3 * ks));
            *(float4*)(out + (size_t)n * DD + hcb) = make_float4(o0, o1, o2, o3);
        }
        __syncthreads();  // protect sh before next node
    }
}

// ---------------- launch ----------------
extern "C" void kernel_launch(void* const* d_in, const int* in_sizes, int n_in,
                              void* d_out, int out_size) {
    const float* h      = (const float*)d_in[0];
    const int*   ei     = (const int*)d_in[1];
    const float* ea     = (const float*)d_in[2];
    const float* g1_Wl  = (const float*)d_in[3];
    const float* g1_bl  = (const float*)d_in[4];
    const float* g1_Wr  = (const float*)d_in[5];
    const float* g1_br  = (const float*)d_in[6];
    const float* g1_We  = (const float*)d_in[7];
    const float* g1_att = (const float*)d_in[8];
    const float* g1_bias= (const float*)d_in[9];
    const float* ln1_g  = (const float*)d_in[10];
    const float* ln1_b  = (const float*)d_in[11];
    const float* g2_Wl  = (const float*)d_in[12];
    const float* g2_bl  = (const float*)d_in[13];
    const float* g2_Wr  = (const float*)d_in[14];
    const float* g2_br  = (const float*)d_in[15];
    const float* g2_We  = (const float*)d_in[16];
    const float* g2_att = (const float*)d_in[17];
    const float* g2_bias= (const float*)d_in[18];
    const float* ln2_g  = (const float*)d_in[19];
    const float* ln2_b  = (const float*)d_in[20];
    float* out = (float*)d_out;

    const int* src = ei;
    const int* dst = ei + EE;

    zero_cnt_kernel<<<(NN + 255) / 256, 256>>>();
    hist_kernel<<<(EE + 255) / 256, 256>>>(dst);
    scan_kernel<<<1, 1024>>>();
    scatter_kernel<<<(EE + 255) / 256, 256>>>(src, dst);

    transform_kernel<<<(NN + 63) / 64, 512>>>(h, g1_Wl, g1_bl, g1_Wr, g1_br);
    gat_kernel<<<2960, 64>>>(ea, g1_We, g1_att, g1_bias, ln1_g, ln1_b,
                             nullptr, nullptr, 0);
    transform_kernel<<<(NN + 63) / 64, 512>>>(nullptr, g2_Wl, g2_bl, g2_Wr, g2_br);
    gat_kernel<<<2960, 64>>>(ea, g2_We, g2_att, g2_bias, ln2_g, ln2_b,
                             h, out, 1);
}

// round 4
// speedup vs baseline: 1.7030x; 1.1546x over previous
#include <cuda_runtime.h>
#include <math.h>

#define NN 50000
#define EE 400000
#define DD 64
#define HH 4
#define CC 64
#define HC 256
#define EDD 16

typedef unsigned long long ull;

// ---------------- static scratch ----------------
__device__ __align__(16) float g_xl[(size_t)NN * HC];
__device__ __align__(16) float g_xr[(size_t)NN * HC];
__device__ __align__(16) float g_mid[(size_t)NN * DD];
__device__ __align__(16) float g_eacsr[(size_t)EE * EDD];  // edge_attr permuted to CSR order
__device__ int g_cnt[NN];
__device__ int g_cursor[NN];
__device__ int g_rowptr[NN + 1];
__device__ int g_esrc[EE];
__device__ int g_eord[EE];

// ---------------- packed f32x2 helpers ----------------
__device__ __forceinline__ ull pk2(float a, float b) {
    ull r; asm("mov.b64 %0, {%1, %2};" : "=l"(r) : "f"(a), "f"(b)); return r;
}
__device__ __forceinline__ ull dup2(float a) {
    ull r; asm("mov.b64 %0, {%1, %1};" : "=l"(r) : "f"(a)); return r;
}
__device__ __forceinline__ float2 up2(ull v) {
    float2 r; asm("mov.b64 {%0, %1}, %2;" : "=f"(r.x), "=f"(r.y) : "l"(v)); return r;
}
__device__ __forceinline__ ull fma2(ull a, ull b, ull c) {
    ull d; asm("fma.rn.f32x2 %0, %1, %2, %3;" : "=l"(d) : "l"(a), "l"(b), "l"(c)); return d;
}

// ---------------- CSR build ----------------
__global__ void zero_cnt_kernel() {
    int i = blockIdx.x * blockDim.x + threadIdx.x;
    if (i < NN) g_cnt[i] = 0;
}

__global__ void hist_kernel(const int* __restrict__ dst) {
    int e = blockIdx.x * blockDim.x + threadIdx.x;
    if (e < EE) atomicAdd(&g_cnt[dst[e]], 1);
}

// single-block scan: 1024 threads, 49 elements each (49*1024 >= NN)
__global__ __launch_bounds__(1024) void scan_kernel() {
    __shared__ int wsum[32];
    int t = threadIdx.x;
    int lane = t & 31, wid = t >> 5;
    const int PER = 49;
    int base = t * PER;

    int s = 0;
#pragma unroll 7
    for (int i = 0; i < PER; i++) {
        int idx = base + i;
        if (idx < NN) s += g_cnt[idx];
    }
    int ws = s;
#pragma unroll
    for (int off = 1; off < 32; off <<= 1) {
        int v = __shfl_up_sync(0xffffffffu, ws, off);
        if (lane >= off) ws += v;
    }
    if (lane == 31) wsum[wid] = ws;
    __syncthreads();
    if (wid == 0) {
        int v = wsum[lane];
        int iv = v;
#pragma unroll
        for (int off = 1; off < 32; off <<= 1) {
            int u = __shfl_up_sync(0xffffffffu, iv, off);
            if (lane >= off) iv += u;
        }
        wsum[lane] = iv - v;  // exclusive
    }
    __syncthreads();
    int offset = wsum[wid] + (ws - s);

    int run = offset;
#pragma unroll 7
    for (int i = 0; i < PER; i++) {
        int idx = base + i;
        if (idx < NN) {
            int v = g_cnt[idx];
            g_rowptr[idx] = run;
            g_cursor[idx] = run;
            run += v;
        }
    }
    if (t == 1023) g_rowptr[NN] = run;
}

__global__ void scatter_kernel(const int* __restrict__ src, const int* __restrict__ dst) {
    int e = blockIdx.x * blockDim.x + threadIdx.x;
    if (e < EE) {
        int d = dst[e];
        int pos = atomicAdd(&g_cursor[d], 1);
        g_esrc[pos] = src[e];
        g_eord[pos] = e;
    }
}

// permute edge_attr rows into CSR order (4 threads per edge, float4 each)
__global__ void permute_ea_kernel(const float* __restrict__ ea) {
    int t = blockIdx.x * blockDim.x + threadIdx.x;
    int pos = t >> 2;
    int c4 = t & 3;
    if (pos < EE) {
        int eid = g_eord[pos];
        ((float4*)g_eacsr)[(size_t)pos * 4 + c4] =
            ((const float4*)ea)[(size_t)eid * 4 + c4];
    }
}

// ---------------- node transform: xl = x@Wl+bl, xr = x@Wr+br ----------------
__global__ __launch_bounds__(512) void transform_kernel(
    const float* __restrict__ x,  // null -> g_mid
    const float* __restrict__ Wl, const float* __restrict__ bl,
    const float* __restrict__ Wr, const float* __restrict__ br)
{
    __shared__ __align__(16) float hs[64 * 64];
    const float* xp = x ? x : g_mid;
    int tid = threadIdx.x;
    int j = tid & 255;
    int isR = tid >> 8;
    const float* W = isR ? Wr : Wl;
    float bj = isR ? br[j] : bl[j];
    float* ob = isR ? g_xr : g_xl;
    int n0 = blockIdx.x * 64;

    ull w2[32];
#pragma unroll
    for (int q = 0; q < 32; q++)
        w2[q] = pk2(W[(2 * q) * HC + j], W[(2 * q + 1) * HC + j]);

    const float4* src4 = (const float4*)(xp + (size_t)n0 * DD);
    int limit4 = (NN - n0) * (DD / 4);
    for (int i = tid; i < 1024; i += 512) {
        float4 v = (i < limit4) ? src4[i] : make_float4(0.f, 0.f, 0.f, 0.f);
        ((float4*)hs)[i] = v;
    }
    __syncthreads();

    int nmax = NN - n0; if (nmax > 64) nmax = 64;
    for (int n = 0; n < nmax; n++) {
        const float4* hrow = (const float4*)(hs + n * 64);
        ull a0 = 0, a1 = 0, a2 = 0, a3 = 0;
#pragma unroll
        for (int q = 0; q < 16; q += 2) {
            float4 h0 = hrow[q], h1 = hrow[q + 1];
            a0 = fma2(pk2(h0.x, h0.y), w2[2 * q + 0], a0);
            a1 = fma2(pk2(h0.z, h0.w), w2[2 * q + 1], a1);
            a2 = fma2(pk2(h1.x, h1.y), w2[2 * q + 2], a2);
            a3 = fma2(pk2(h1.z, h1.w), w2[2 * q + 3], a3);
        }
        float2 f0 = up2(a0), f1 = up2(a1), f2 = up2(a2), f3 = up2(a3);
        ob[(size_t)(n0 + n) * HC + j] =
            bj + ((f0.x + f0.y) + (f1.x + f1.y)) + ((f2.x + f2.y) + (f3.x + f3.y));
    }
}

// ---------------- fused GATv2 aggregate + head-mean + bias + LN + res + GELU ----
// block = 64 threads = 2 warps per node (grid-stride).
// warp w -> heads {2w, 2w+1}: lanes 0-15 first head, 16-31 second.
// lane owns 4 channels: hcb = (lane&15)*4, cb = head*64 + hcb.
// ea rows staged through smem in chunks of 32 edges; ez uses k-pair packed fma2.
__global__ __launch_bounds__(64) void gat_kernel(
    const float* __restrict__ We,         // [16,256]
    const float* __restrict__ att,        // [4,64]
    const float* __restrict__ bias,       // [64]
    const float* __restrict__ lng, const float* __restrict__ lnb,
    const float* __restrict__ residual,   // null for layer 1
    float* __restrict__ out_ext, int use_ext)
{
    __shared__ __align__(16) float sh_ea[32 * EDD];  // 2KB: 32 edges' attr rows
    __shared__ float sh[64];
    int warp = threadIdx.x >> 5;
    int lane = threadIdx.x & 31;
    int head = warp * 2 + (lane >> 4);
    int hcb = (lane & 15) * 4;
    int cb = head * CC + hcb;
    float* out = use_ext ? out_ext : g_mid;

    // We cache: k-pair packed. w_[kp][ch] = (We[2kp][c], We[2kp+1][c])
    ull w0[8], w1[8], w2r[8], w3[8];
#pragma unroll
    for (int kp = 0; kp < 8; kp++) {
        float4 wa = *(const float4*)(We + (2 * kp) * HC + cb);
        float4 wb = *(const float4*)(We + (2 * kp + 1) * HC + cb);
        w0[kp] = pk2(wa.x, wb.x);
        w1[kp] = pk2(wa.y, wb.y);
        w2r[kp] = pk2(wa.z, wb.z);
        w3[kp] = pk2(wa.w, wb.w);
    }
    float4 attv = *(const float4*)(att + head * CC + hcb);
    float4 bi4 = *(const float4*)(bias + hcb);
    float4 lg4 = *(const float4*)(lng + hcb);
    float4 lb4 = *(const float4*)(lnb + hcb);

    for (int n = blockIdx.x; n < NN; n += gridDim.x) {
        int e0 = g_rowptr[n], e1 = g_rowptr[n + 1];

        float4 xr4 = *(const float4*)(g_xr + (size_t)n * HC + cb);

        ull acc0 = 0, acc1 = 0;
        float den = 0.f;

        for (int ch0 = e0; ch0 < e1; ch0 += 32) {
            int cnt = min(32, e1 - ch0);
            __syncthreads();  // sh_ea free from previous readers
            {
                const float4* ga = ((const float4*)g_eacsr) + (size_t)ch0 * 4;
                for (int i = threadIdx.x; i < cnt * 4; i += 64)
                    ((float4*)sh_ea)[i] = ga[i];
            }
            __syncthreads();

            // 1-deep pipeline on the xl gather
            float4 xl4 = make_float4(0.f, 0.f, 0.f, 0.f);
            {
                int s0 = g_esrc[ch0];
                xl4 = *(const float4*)(g_xl + (size_t)s0 * HC + cb);
            }
            for (int i = 0; i < cnt; i++) {
                float4 xln = make_float4(0.f, 0.f, 0.f, 0.f);
                if (i + 1 < cnt) {
                    int sn = g_esrc[ch0 + i + 1];
                    xln = *(const float4*)(g_xl + (size_t)sn * HC + cb);
                }

                // ez via k-pair packed fma2 (smem broadcast reads, no shfl)
                const ull* sea = ((const ull*)sh_ea) + (i << 3);
                ull ez0 = 0, ez1 = 0, ez2 = 0, ez3 = 0;
#pragma unroll
                for (int kp = 0; kp < 8; kp++) {
                    ull ea2 = sea[kp];
                    ez0 = fma2(ea2, w0[kp], ez0);
                    ez1 = fma2(ea2, w1[kp], ez1);
                    ez2 = fma2(ea2, w2r[kp], ez2);
                    ez3 = fma2(ea2, w3[kp], ez3);
                }
                float2 z0 = up2(ez0), z1 = up2(ez1), z2 = up2(ez2), z3 = up2(ez3);
                float y0 = xl4.x + xr4.x + (z0.x + z0.y);
                float y1 = xl4.y + xr4.y + (z1.x + z1.y);
                float y2 = xl4.z + xr4.z + (z2.x + z2.y);
                float y3 = xl4.w + xr4.w + (z3.x + z3.y);
                float l0 = fmaxf(y0, 0.2f * y0);
                float l1 = fmaxf(y1, 0.2f * y1);
                float l2 = fmaxf(y2, 0.2f * y2);
                float l3 = fmaxf(y3, 0.2f * y3);
                float ap = l0 * attv.x;
                ap = fmaf(l1, attv.y, ap);
                ap = fmaf(l2, attv.z, ap);
                ap = fmaf(l3, attv.w, ap);
                // reduce over 16 lanes of this head (all 32 lanes execute)
                ap += __shfl_xor_sync(0xffffffffu, ap, 1);
                ap += __shfl_xor_sync(0xffffffffu, ap, 2);
                ap += __shfl_xor_sync(0xffffffffu, ap, 4);
                ap += __shfl_xor_sync(0xffffffffu, ap, 8);

                float ex = __expf(ap);  // softmax w/o max-shift: scale-invariant
                den += ex;
                ull ex2 = dup2(ex);
                acc0 = fma2(pk2(xl4.x, xl4.y), ex2, acc0);
                acc1 = fma2(pk2(xl4.z, xl4.w), ex2, acc1);

                xl4 = xln;
            }
        }

        // normalize per head
        float inv = 1.f / (den + 1e-16f);
        float2 a0 = up2(acc0), a1 = up2(acc1);
        float r0 = a0.x * inv, r1 = a0.y * inv, r2 = a1.x * inv, r3 = a1.y * inv;

        // sum the two heads of this warp (all 32 lanes execute)
        r0 += __shfl_xor_sync(0xffffffffu, r0, 16);
        r1 += __shfl_xor_sync(0xffffffffu, r1, 16);
        r2 += __shfl_xor_sync(0xffffffffu, r2, 16);
        r3 += __shfl_xor_sync(0xffffffffu, r3, 16);

        if (warp == 1 && lane < 16)
            *(float4*)(sh + hcb) = make_float4(r0, r1, r2, r3);
        __syncthreads();
        if (warp == 0 && lane < 16) {
            const unsigned M16 = 0x0000ffffu;  // only lanes 0-15 execute here
            float4 o = *(const float4*)(sh + hcb);
            r0 = 0.25f * (r0 + o.x) + bi4.x;
            r1 = 0.25f * (r1 + o.y) + bi4.y;
            r2 = 0.25f * (r2 + o.z) + bi4.z;
            r3 = 0.25f * (r3 + o.w) + bi4.w;
            float m = r0 + r1 + r2 + r3;
            m += __shfl_xor_sync(M16, m, 1);
            m += __shfl_xor_sync(M16, m, 2);
            m += __shfl_xor_sync(M16, m, 4);
            m += __shfl_xor_sync(M16, m, 8);
            m *= (1.f / 64.f);
            float d0 = r0 - m, d1 = r1 - m, d2 = r2 - m, d3 = r3 - m;
            float v = d0 * d0;
            v = fmaf(d1, d1, v); v = fmaf(d2, d2, v); v = fmaf(d3, d3, v);
            v += __shfl_xor_sync(M16, v, 1);
            v += __shfl_xor_sync(M16, v, 2);
            v += __shfl_xor_sync(M16, v, 4);
            v += __shfl_xor_sync(M16, v, 8);
            v *= (1.f / 64.f);
            float rstd = rsqrtf(v + 1e-5f);

            float y0 = d0 * rstd * lg4.x + lb4.x;
            float y1 = d1 * rstd * lg4.y + lb4.y;
            float y2 = d2 * rstd * lg4.z + lb4.z;
            float y3 = d3 * rstd * lg4.w + lb4.w;
            if (residual) {
                float4 rs = *(const float4*)(residual + (size_t)n * DD + hcb);
                y0 += rs.x; y1 += rs.y; y2 += rs.z; y3 += rs.w;
            }
            const float ks = 0.70710678118654752f;
            float o0 = 0.5f * y0 * (1.f + erff(y0 * ks));
            float o1 = 0.5f * y1 * (1.f + erff(y1 * ks));
            float o2 = 0.5f * y2 * (1.f + erff(y2 * ks));
            float o3 = 0.5f * y3 * (1.f + erff(y3 * ks));
            *(float4*)(out + (size_t)n * DD + hcb) = make_float4(o0, o1, o2, o3);
        }
        __syncthreads();  // protect sh before next node
    }
}

// ---------------- launch ----------------
extern "C" void kernel_launch(void* const* d_in, const int* in_sizes, int n_in,
                              void* d_out, int out_size) {
    const float* h      = (const float*)d_in[0];
    const int*   ei     = (const int*)d_in[1];
    const float* ea     = (const float*)d_in[2];
    const float* g1_Wl  = (const float*)d_in[3];
    const float* g1_bl  = (const float*)d_in[4];
    const float* g1_Wr  = (const float*)d_in[5];
    const float* g1_br  = (const float*)d_in[6];
    const float* g1_We  = (const float*)d_in[7];
    const float* g1_att = (const float*)d_in[8];
    const float* g1_bias= (const float*)d_in[9];
    const float* ln1_g  = (const float*)d_in[10];
    const float* ln1_b  = (const float*)d_in[11];
    const float* g2_Wl  = (const float*)d_in[12];
    const float* g2_bl  = (const float*)d_in[13];
    const float* g2_Wr  = (const float*)d_in[14];
    const float* g2_br  = (const float*)d_in[15];
    const float* g2_We  = (const float*)d_in[16];
    const float* g2_att = (const float*)d_in[17];
    const float* g2_bias= (const float*)d_in[18];
    const float* ln2_g  = (const float*)d_in[19];
    const float* ln2_b  = (const float*)d_in[20];
    float* out = (float*)d_out;

    const int* src = ei;
    const int* dst = ei + EE;

    zero_cnt_kernel<<<(NN + 255) / 256, 256>>>();
    hist_kernel<<<(EE + 255) / 256, 256>>>(dst);
    scan_kernel<<<1, 1024>>>();
    scatter_kernel<<<(EE + 255) / 256, 256>>>(src, dst);
    permute_ea_kernel<<<(EE * 4 + 255) / 256, 256>>>(ea);

    transform_kernel<<<(NN + 63) / 64, 512>>>(h, g1_Wl, g1_bl, g1_Wr, g1_br);
    gat_kernel<<<6250, 64>>>(g1_We, g1_att, g1_bias, ln1_g, ln1_b,
                             nullptr, nullptr, 0);
    transform_kernel<<<(NN + 63) / 64, 512>>>(nullptr, g2_Wl, g2_bl, g2_Wr, g2_br);
    gat_kernel<<<6250, 64>>>(g2_We, g2_att, g2_bias, ln2_g, ln2_b,
                             h, out, 1);
}